// round 1
// baseline (speedup 1.0000x reference)
#include <cuda_runtime.h>
#include <cstdint>

#define NB 64
#define NT 100
#define NA 8732

// Scratch (static __device__ — no allocation allowed)
__device__ float              g_gt_ov[NB * NA];
__device__ int                g_gt_idx[NB * NA];
__device__ unsigned long long g_best[NB * NT];   // per (b,t): (iou_bits<<32)|(0xFFFFFFFF - anchor)

// -------------------------------------------------------------------------
// Kernel 0: reset per-target best keys (must happen every launch — graph replays)
// -------------------------------------------------------------------------
__global__ void k_init() {
    int i = blockIdx.x * blockDim.x + threadIdx.x;
    if (i < NB * NT) g_best[i] = 0ull;
}

// -------------------------------------------------------------------------
// Kernel 1: main IoU pass.
//   grid = (ceil(A/256), B), block = 256. Thread owns one anchor.
//   - per-anchor argmax over t  -> g_gt_ov / g_gt_idx   (strict >, keeps first t)
//   - per-target argmax over a  -> guarded atomicMax on packed u64 key
//     key = (float_bits(iou) << 32) | (0xFFFFFFFF - a)
//     iou >= 0 so float bits are order-preserving; low word makes ties
//     resolve to the LOWEST anchor index (jnp.argmax semantics).
// -------------------------------------------------------------------------
__global__ __launch_bounds__(256) void k_main(const float* __restrict__ targets,
                                              const float* __restrict__ anchors) {
    __shared__ float4 s_box[NT];    // x1,y1,x2,y2
    __shared__ float  s_area[NT];   // precomputed target area

    const int tid = threadIdx.x;
    const int b   = blockIdx.y;

    for (int t = tid; t < NT; t += blockDim.x) {
        const float* tp = targets + ((size_t)b * NT + t) * 5;
        float x1 = tp[0], y1 = tp[1], x2 = tp[2], y2 = tp[3];
        s_box[t]  = make_float4(x1, y1, x2, y2);
        s_area[t] = __fmul_rn(__fsub_rn(x2, x1), __fsub_rn(y2, y1));
    }
    __syncthreads();

    const int a = blockIdx.x * blockDim.x + tid;
    if (a >= NA) return;

    // anchor point-form (replicate reference exactly; *0.5 is exact)
    const float4 an = reinterpret_cast<const float4*>(anchors)[a];
    const float hw = __fmul_rn(an.z, 0.5f);
    const float hh = __fmul_rn(an.w, 0.5f);
    const float ax1 = __fsub_rn(an.x, hw), ay1 = __fsub_rn(an.y, hh);
    const float ax2 = __fadd_rn(an.x, hw), ay2 = __fadd_rn(an.y, hh);
    // reference recomputes area from point-form coords — do the same
    const float areaA = __fmul_rn(__fsub_rn(ax2, ax1), __fsub_rn(ay2, ay1));

    float best_ov = -1.0f;
    int   best_t  = 0;
    const unsigned long long lowkey = (unsigned long long)(0xFFFFFFFFu - (unsigned)a);
    unsigned long long* bestp = &g_best[b * NT];

#pragma unroll 4
    for (int t = 0; t < NT; ++t) {
        const float4 tb   = s_box[t];
        const float areaB = s_area[t];
        const float tlx = fmaxf(tb.x, ax1);
        const float tly = fmaxf(tb.y, ay1);
        const float brx = fminf(tb.z, ax2);
        const float bry = fminf(tb.w, ay2);
        const float dx = fmaxf(__fsub_rn(brx, tlx), 0.0f);
        const float dy = fmaxf(__fsub_rn(bry, tly), 0.0f);
        const float inter = __fmul_rn(dx, dy);
        const float denom = __fsub_rn(__fadd_rn(areaB, areaA), inter);
        const float iou   = __fdiv_rn(inter, denom);

        if (iou > best_ov) { best_ov = iou; best_t = t; }   // first-t wins ties

        const unsigned long long key =
            ((unsigned long long)__float_as_uint(iou) << 32) | lowkey;
        const unsigned long long cur = bestp[t];            // stale-safe guard (monotone)
        if (key > cur) atomicMax(bestp + t, key);
    }

    g_gt_ov[(size_t)b * NA + a]  = best_ov;
    g_gt_idx[(size_t)b * NA + a] = best_t;
}

// -------------------------------------------------------------------------
// Kernel 2: finalize.
//   Rebuild anchor_index[b][t] from keys; override scan t ascending so the
//   LAST t writing a given anchor wins (in-order scatter semantics); then
//   encode loc + conf.
// -------------------------------------------------------------------------
__global__ __launch_bounds__(256) void k_final(const float* __restrict__ targets,
                                               const float* __restrict__ anchors,
                                               float* __restrict__ out) {
    __shared__ int    s_aidx[NT];
    __shared__ float4 s_box[NT];
    __shared__ float  s_lab[NT];

    const int tid = threadIdx.x;
    const int b   = blockIdx.y;

    for (int t = tid; t < NT; t += blockDim.x) {
        unsigned long long k = g_best[b * NT + t];
        s_aidx[t] = (int)(0xFFFFFFFFu - (unsigned)(k & 0xFFFFFFFFull));
        const float* tp = targets + ((size_t)b * NT + t) * 5;
        s_box[t] = make_float4(tp[0], tp[1], tp[2], tp[3]);
        s_lab[t] = tp[4];
    }
    __syncthreads();

    const int a = blockIdx.x * blockDim.x + tid;
    if (a >= NA) return;

    int   gi = g_gt_idx[(size_t)b * NA + a];
    float ov = g_gt_ov[(size_t)b * NA + a];

    int bt = -1;
#pragma unroll
    for (int t = 0; t < NT; ++t) bt = (s_aidx[t] == a) ? t : bt;  // last t wins
    if (bt >= 0) { gi = bt; ov = 1.0f; }

    const float4 m   = s_box[gi];
    const float  lab = s_lab[gi];
    const float4 an  = reinterpret_cast<const float4*>(anchors)[a];

    const float cx = __fmul_rn(__fadd_rn(m.x, m.z), 0.5f);
    const float cy = __fmul_rn(__fadd_rn(m.y, m.w), 0.5f);
    const float w  = __fsub_rn(m.z, m.x);
    const float h  = __fsub_rn(m.w, m.y);

    const float lx = __fdiv_rn(__fsub_rn(cx, an.x), __fmul_rn(0.1f, an.z));
    const float ly = __fdiv_rn(__fsub_rn(cy, an.y), __fmul_rn(0.1f, an.w));
    const float lw = __fdiv_rn(logf(__fdiv_rn(w, an.z)), 0.2f);
    const float lh = __fdiv_rn(logf(__fdiv_rn(h, an.w)), 0.2f);

    const size_t base = (size_t)b * NA + a;
    reinterpret_cast<float4*>(out)[base] = make_float4(lx, ly, lw, lh);

    const float conf = (ov < 0.5f) ? 0.0f : __fadd_rn(lab, 1.0f);
    out[(size_t)NB * NA * 4 + base] = conf;
}

// -------------------------------------------------------------------------
extern "C" void kernel_launch(void* const* d_in, const int* in_sizes, int n_in,
                              void* d_out, int out_size) {
    const float* targets = (const float*)d_in[0];   // [B, T, 5]
    const float* anchors = (const float*)d_in[1];   // [A, 4]
    float* out = (float*)d_out;                     // [B*A*4 loc][B*A conf]

    k_init<<<(NB * NT + 255) / 256, 256>>>();
    dim3 grid((NA + 255) / 256, NB);
    k_main<<<grid, 256>>>(targets, anchors);
    k_final<<<grid, 256>>>(targets, anchors, out);
}

// round 2
// speedup vs baseline: 1.2786x; 1.2786x over previous
#include <cuda_runtime.h>
#include <cstdint>

#define NB   64
#define NT   100
#define NA   8732
#define NBLK ((NA + 255) / 256)   // 35 anchor tiles

// Scratch (static __device__ — allocation is forbidden).
// g_part is fully overwritten every replay -> no init kernel needed.
__device__ float              g_gt_ov [NB * NA];
__device__ int                g_gt_idx[NB * NA];
__device__ unsigned long long g_part  [NBLK * NB * NT];  // per (tile,b,t) best key

// key = (float_bits(iou) << 32) | (0xFFFFFFFF - anchor)
// iou >= 0 so float bits preserve order; low word => ties pick LOWEST anchor
// (jnp.argmax semantics). max over keys is associative -> deterministic merge.

// -------------------------------------------------------------------------
// Kernel 1: IoU pass. grid = (NBLK, NB), block = 256. Thread owns one anchor.
//   - per-anchor argmax over t (registers, strict > keeps first t)
//   - per-target argmax over anchors: shared guard + shared atomicMax,
//     block result written (plain STG) to g_part.
// -------------------------------------------------------------------------
__global__ __launch_bounds__(256) void k_main(const float* __restrict__ targets,
                                              const float* __restrict__ anchors) {
    __shared__ float4             s_box [NT];
    __shared__ float              s_area[NT];
    __shared__ unsigned long long s_best[NT];

    const int tid = threadIdx.x;
    const int b   = blockIdx.y;

    for (int t = tid; t < NT; t += blockDim.x) {
        const float* tp = targets + ((size_t)b * NT + t) * 5;
        float x1 = tp[0], y1 = tp[1], x2 = tp[2], y2 = tp[3];
        s_box[t]  = make_float4(x1, y1, x2, y2);
        s_area[t] = __fmul_rn(__fsub_rn(x2, x1), __fsub_rn(y2, y1));
        s_best[t] = 0ull;
    }
    __syncthreads();

    const int  a     = blockIdx.x * blockDim.x + tid;
    const bool valid = (a < NA);

    if (valid) {
        // anchor point-form, replicating reference arithmetic exactly
        const float4 an = reinterpret_cast<const float4*>(anchors)[a];
        const float hw  = __fmul_rn(an.z, 0.5f);
        const float hh  = __fmul_rn(an.w, 0.5f);
        const float ax1 = __fsub_rn(an.x, hw), ay1 = __fsub_rn(an.y, hh);
        const float ax2 = __fadd_rn(an.x, hw), ay2 = __fadd_rn(an.y, hh);
        const float areaA = __fmul_rn(__fsub_rn(ax2, ax1), __fsub_rn(ay2, ay1));

        float best_ov = -1.0f;
        int   best_t  = 0;
        const unsigned long long lowkey =
            (unsigned long long)(0xFFFFFFFFu - (unsigned)a);

#pragma unroll 4
        for (int t = 0; t < NT; ++t) {
            const float4 tb   = s_box[t];
            const float areaB = s_area[t];
            const float tlx = fmaxf(tb.x, ax1);
            const float tly = fmaxf(tb.y, ay1);
            const float brx = fminf(tb.z, ax2);
            const float bry = fminf(tb.w, ay2);
            const float dx  = fmaxf(__fsub_rn(brx, tlx), 0.0f);
            const float dy  = fmaxf(__fsub_rn(bry, tly), 0.0f);
            const float inter = __fmul_rn(dx, dy);
            const float denom = __fsub_rn(__fadd_rn(areaB, areaA), inter);
            const float iou   = __fdiv_rn(inter, denom);

            if (iou > best_ov) { best_ov = iou; best_t = t; }  // first-t wins

            const unsigned long long key =
                ((unsigned long long)__float_as_uint(iou) << 32) | lowkey;
            if (key > s_best[t]) atomicMax(&s_best[t], key);   // shared, rare
        }

        g_gt_ov [(size_t)b * NA + a] = best_ov;
        g_gt_idx[(size_t)b * NA + a] = best_t;
    }

    __syncthreads();
    for (int t = tid; t < NT; t += blockDim.x)
        g_part[((size_t)blockIdx.x * NB + b) * NT + t] = s_best[t];
}

// -------------------------------------------------------------------------
// Kernel 2: finalize. grid = (NBLK, NB), block = 256.
//   Reduce the 35 partial keys per (b,t), rebuild anchor_index, apply the
//   scatter override (ascending t => last-t-wins, matching in-order scatter),
//   then encode loc + conf.
// -------------------------------------------------------------------------
__global__ __launch_bounds__(256) void k_final(const float* __restrict__ targets,
                                               const float* __restrict__ anchors,
                                               float* __restrict__ out) {
    __shared__ int    s_aidx[NT];
    __shared__ float4 s_box [NT];
    __shared__ float  s_lab [NT];

    const int tid = threadIdx.x;
    const int b   = blockIdx.y;

    for (int t = tid; t < NT; t += blockDim.x) {
        unsigned long long m = 0ull;
#pragma unroll
        for (int p = 0; p < NBLK; ++p) {
            unsigned long long v = g_part[((size_t)p * NB + b) * NT + t];
            m = (v > m) ? v : m;
        }
        s_aidx[t] = (int)(0xFFFFFFFFu - (unsigned)(m & 0xFFFFFFFFull));
        const float* tp = targets + ((size_t)b * NT + t) * 5;
        s_box[t] = make_float4(tp[0], tp[1], tp[2], tp[3]);
        s_lab[t] = tp[4];
    }
    __syncthreads();

    const int a = blockIdx.x * blockDim.x + tid;
    if (a >= NA) return;

    int   gi = g_gt_idx[(size_t)b * NA + a];
    float ov = g_gt_ov [(size_t)b * NA + a];

    int bt = -1;
#pragma unroll
    for (int t = 0; t < NT; ++t) bt = (s_aidx[t] == a) ? t : bt;  // last t wins
    if (bt >= 0) { gi = bt; ov = 1.0f; }

    const float4 m   = s_box[gi];
    const float  lab = s_lab[gi];
    const float4 an  = reinterpret_cast<const float4*>(anchors)[a];

    const float cx = __fmul_rn(__fadd_rn(m.x, m.z), 0.5f);
    const float cy = __fmul_rn(__fadd_rn(m.y, m.w), 0.5f);
    const float w  = __fsub_rn(m.z, m.x);
    const float h  = __fsub_rn(m.w, m.y);

    const float lx = __fdiv_rn(__fsub_rn(cx, an.x), __fmul_rn(0.1f, an.z));
    const float ly = __fdiv_rn(__fsub_rn(cy, an.y), __fmul_rn(0.1f, an.w));
    const float lw = __fdiv_rn(logf(__fdiv_rn(w, an.z)), 0.2f);
    const float lh = __fdiv_rn(logf(__fdiv_rn(h, an.w)), 0.2f);

    const size_t base = (size_t)b * NA + a;
    reinterpret_cast<float4*>(out)[base] = make_float4(lx, ly, lw, lh);

    const float conf = (ov < 0.5f) ? 0.0f : __fadd_rn(lab, 1.0f);
    out[(size_t)NB * NA * 4 + base] = conf;
}

// -------------------------------------------------------------------------
extern "C" void kernel_launch(void* const* d_in, const int* in_sizes, int n_in,
                              void* d_out, int out_size) {
    const float* targets = (const float*)d_in[0];   // [B, T, 5]
    const float* anchors = (const float*)d_in[1];   // [A, 4]
    float* out = (float*)d_out;                     // [B*A*4 loc][B*A conf]

    dim3 grid(NBLK, NB);
    k_main <<<grid, 256>>>(targets, anchors);
    k_final<<<grid, 256>>>(targets, anchors, out);
}

// round 4
// speedup vs baseline: 2.7670x; 2.1641x over previous
#include <cuda_runtime.h>
#include <cstdint>

#define NB   64
#define NT   100
#define NA   8732
#define NBLK ((NA + 255) / 256)   // 35 anchor tiles

// Scratch (static __device__ — allocation is forbidden). Everything here is
// fully (over)written each replay before being read — no init kernel needed.
__device__ float              g_gt_ov [NB * NA];
__device__ int                g_gt_idx[NB * NA];
__device__ unsigned long long g_part  [NBLK * NB * NT];  // per (tile,b,t) best key
__device__ int                g_ovr   [NB * NA];         // override target id, -1 = none

// key = (iou_bits << 32) | (0xFFFFFFFF - anchor).  iou >= 0 so float bits are
// order-preserving; low word makes ties resolve to the LOWEST anchor index
// (jnp.argmax semantics). max over keys is associative -> deterministic merge.

// Exactly-rounded f32 division, fast path only (no FCHK / no branch).
// Valid because denom is normal & in [4e-4, 2.4] and inter in [0, 1.2]:
// identical sequence to ptxas's div.rn.f32 fast path.
__device__ __forceinline__ float fdiv_rn_fast(float x, float d) {
    float y0;
    asm("rcp.approx.f32 %0, %1;" : "=f"(y0) : "f"(d));
    const float e  = __fmaf_rn(-d, y0, 1.0f);
    const float y1 = __fmaf_rn(y0, e, y0);
    const float q0 = __fmul_rn(x, y1);
    const float r  = __fmaf_rn(-d, q0, x);
    return __fmaf_rn(r, y1, q0);
}

// -------------------------------------------------------------------------
// Kernel 1: IoU pass. grid = (NBLK, NB), block = 256. Thread owns one anchor.
//   - per-anchor argmax over t in registers (strict >, keeps first/lowest t)
//   - per-target argmax over anchors: REDUX.MAX + ballot winner election,
//     per-warp key to shared, block merge -> g_part. Branch-free hot loop.
//   - also clears g_ovr[b][a] = -1 (each (b,a) owned by exactly one thread)
// -------------------------------------------------------------------------
__global__ __launch_bounds__(256) void k_main(const float* __restrict__ targets,
                                              const float* __restrict__ anchors) {
    __shared__ float4             s_box [NT];
    __shared__ float              s_area[NT];
    __shared__ unsigned long long s_key [8 * NT];   // [warp][t]

    const int tid  = threadIdx.x;
    const int wid  = tid >> 5;
    const int lane = tid & 31;
    const int b    = blockIdx.y;

    for (int t = tid; t < NT; t += 256) {
        const float* tp = targets + ((size_t)b * NT + t) * 5;
        float x1 = tp[0], y1 = tp[1], x2 = tp[2], y2 = tp[3];
        s_box[t]  = make_float4(x1, y1, x2, y2);
        s_area[t] = __fmul_rn(__fsub_rn(x2, x1), __fsub_rn(y2, y1));
    }
    for (int i = tid; i < 8 * NT; i += 256) s_key[i] = 0ull;
    __syncthreads();

    const int  a        = blockIdx.x * 256 + tid;
    const bool valid    = (a < NA);
    const int  a_ld     = valid ? a : (NA - 1);      // clamp OOB lanes (dup of last)
    const int  warp_a0  = blockIdx.x * 256 + wid * 32;
    const bool w_store  = (lane == 0) && (warp_a0 < NA);
    const unsigned inv_base = 0xFFFFFFFFu - (unsigned)warp_a0;  // lowkey = inv_base - wl

    // anchor point-form, replicating reference arithmetic exactly
    const float4 an = reinterpret_cast<const float4*>(anchors)[a_ld];
    const float hw  = __fmul_rn(an.z, 0.5f);
    const float hh  = __fmul_rn(an.w, 0.5f);
    const float ax1 = __fsub_rn(an.x, hw), ay1 = __fsub_rn(an.y, hh);
    const float ax2 = __fadd_rn(an.x, hw), ay2 = __fadd_rn(an.y, hh);
    const float areaA = __fmul_rn(__fsub_rn(ax2, ax1), __fsub_rn(ay2, ay1));

    float best_ov = -1.0f;
    int   best_t  = 0;

#pragma unroll 4
    for (int t = 0; t < NT; ++t) {
        const float4 tb   = s_box[t];
        const float areaB = s_area[t];
        const float tlx = fmaxf(tb.x, ax1);
        const float tly = fmaxf(tb.y, ay1);
        const float brx = fminf(tb.z, ax2);
        const float bry = fminf(tb.w, ay2);
        const float dx  = fmaxf(__fsub_rn(brx, tlx), 0.0f);
        const float dy  = fmaxf(__fsub_rn(bry, tly), 0.0f);
        const float inter = __fmul_rn(dx, dy);
        const float denom = __fsub_rn(__fadd_rn(areaB, areaA), inter);
        const float iou   = fdiv_rn_fast(inter, denom);

        // per-anchor argmax (select, no branch)
        const bool gt = (iou > best_ov);
        best_ov = gt ? iou : best_ov;
        best_t  = gt ? t   : best_t;

        // per-target warp argmax: max iou, tie -> lowest lane (= lowest anchor).
        // OOB lanes duplicate the last valid anchor's iou, so ffs can never
        // elect an OOB lane over the valid lane holding the same value.
        const unsigned ib   = __float_as_uint(iou);
        const unsigned wmax = __reduce_max_sync(0xFFFFFFFFu, ib);
        const unsigned mset = __ballot_sync(0xFFFFFFFFu, ib == wmax);
        const int      wl   = __ffs(mset) - 1;
        const unsigned long long key =
            ((unsigned long long)wmax << 32) |
            (unsigned long long)(inv_base - (unsigned)wl);
        if (w_store) s_key[wid * NT + t] = key;       // predicated STS.64
    }

    if (valid) {
        g_gt_ov [(size_t)b * NA + a] = best_ov;
        g_gt_idx[(size_t)b * NA + a] = best_t;
        g_ovr   [(size_t)b * NA + a] = -1;            // cleared for k_merge scatter
    }

    __syncthreads();
    // merge 8 warps -> one key per t for this anchor tile
    if (tid < NT) {
        unsigned long long m = 0ull;
#pragma unroll
        for (int w = 0; w < 8; ++w) {
            unsigned long long v = s_key[w * NT + tid];
            m = (v > m) ? v : m;
        }
        g_part[((size_t)blockIdx.x * NB + b) * NT + tid] = m;
    }
}

// -------------------------------------------------------------------------
// Kernel 2: merge tiles + scatter override. 6400 threads, one per (b,t).
//   anchor_index[b][t] = argmax over anchors; then last-t-wins scatter via
//   atomicMax on t (ascending-t in-order scatter == max-t winner).
// -------------------------------------------------------------------------
__global__ __launch_bounds__(256) void k_merge() {
    const int i = blockIdx.x * 256 + threadIdx.x;
    if (i >= NB * NT) return;
    const int b = i / NT;
    const int t = i - b * NT;

    unsigned long long m = 0ull;
#pragma unroll
    for (int p = 0; p < NBLK; ++p) {
        unsigned long long v = g_part[((size_t)p * NB + b) * NT + t];
        m = (v > m) ? v : m;
    }
    const int aidx = (int)(0xFFFFFFFFu - (unsigned)(m & 0xFFFFFFFFull));
    atomicMax(&g_ovr[(size_t)b * NA + aidx], t);
}

// -------------------------------------------------------------------------
// Kernel 3: finalize / encode. grid = (NBLK, NB), block = 256.
// -------------------------------------------------------------------------
__global__ __launch_bounds__(256) void k_final(const float* __restrict__ targets,
                                               const float* __restrict__ anchors,
                                               float* __restrict__ out) {
    __shared__ float4 s_box[NT];
    __shared__ float  s_lab[NT];

    const int tid = threadIdx.x;
    const int b   = blockIdx.y;

    for (int t = tid; t < NT; t += 256) {
        const float* tp = targets + ((size_t)b * NT + t) * 5;
        s_box[t] = make_float4(tp[0], tp[1], tp[2], tp[3]);
        s_lab[t] = tp[4];
    }
    __syncthreads();

    const int a = blockIdx.x * 256 + tid;
    if (a >= NA) return;

    int   gi = g_gt_idx[(size_t)b * NA + a];
    float ov = g_gt_ov [(size_t)b * NA + a];
    const int ovr = g_ovr[(size_t)b * NA + a];
    if (ovr >= 0) { gi = ovr; ov = 1.0f; }

    const float4 m   = s_box[gi];
    const float  lab = s_lab[gi];
    const float4 an  = reinterpret_cast<const float4*>(anchors)[a];

    const float cx = __fmul_rn(__fadd_rn(m.x, m.z), 0.5f);
    const float cy = __fmul_rn(__fadd_rn(m.y, m.w), 0.5f);
    const float w  = __fsub_rn(m.z, m.x);
    const float h  = __fsub_rn(m.w, m.y);

    const float lx = __fdiv_rn(__fsub_rn(cx, an.x), __fmul_rn(0.1f, an.z));
    const float ly = __fdiv_rn(__fsub_rn(cy, an.y), __fmul_rn(0.1f, an.w));
    const float lw = __fdiv_rn(logf(__fdiv_rn(w, an.z)), 0.2f);
    const float lh = __fdiv_rn(logf(__fdiv_rn(h, an.w)), 0.2f);

    const size_t base = (size_t)b * NA + a;
    reinterpret_cast<float4*>(out)[base] = make_float4(lx, ly, lw, lh);

    const float conf = (ov < 0.5f) ? 0.0f : __fadd_rn(lab, 1.0f);
    out[(size_t)NB * NA * 4 + base] = conf;
}

// -------------------------------------------------------------------------
extern "C" void kernel_launch(void* const* d_in, const int* in_sizes, int n_in,
                              void* d_out, int out_size) {
    const float* targets = (const float*)d_in[0];   // [B, T, 5]
    const float* anchors = (const float*)d_in[1];   // [A, 4]
    float* out = (float*)d_out;                     // [B*A*4 loc][B*A conf]

    dim3 grid(NBLK, NB);
    k_main <<<grid, 256>>>(targets, anchors);
    k_merge<<<(NB * NT + 255) / 256, 256>>>();
    k_final<<<grid, 256>>>(targets, anchors, out);
}